// round 5
// baseline (speedup 1.0000x reference)
#include <cuda_runtime.h>
#include <cuda_fp16.h>
#include <cstdint>

#define N_NODES 100000
#define N_EDGES 3200000
#define N_GRAPHS 1024
#define HID 64

// ---------------------------------------------------------------------------
// Scratch (device globals; no allocations allowed)
// ---------------------------------------------------------------------------
__device__ int     g_deg[N_NODES];
__device__ int     g_off[N_NODES + 1];
__device__ int     g_rank[N_EDGES];          // per-edge rank within its dst bucket
__device__ int     g_srcs[N_EDGES];          // src ids grouped by dst (CSR)
__device__ uint4   g_xh[N_NODES];            // x padded to 8 halfs (16B/node)
__device__ float   g_z1[N_NODES * 5];        // x + agg1
__device__ __half2 g_h1h[N_NODES * (HID/2)]; // layer-1 output (fp16)
__device__ float   g_z2[N_NODES * HID];      // h1 + agg2 (fp32)
__device__ float   g_gsum[N_GRAPHS * HID];
__device__ float   g_gcnt[N_GRAPHS];

// ---------------------------------------------------------------------------
// Pack x (fp32 [N][5]) into fp16 [N][8] rows (one 16B vector per node)
// ---------------------------------------------------------------------------
__global__ void xprep_kernel(const float* __restrict__ x) {
    int n = blockIdx.x * blockDim.x + threadIdx.x;
    if (n >= N_NODES) return;
    const float* xs = x + n * 5;
    __half2 h0 = __floats2half2_rn(xs[0], xs[1]);
    __half2 h1 = __floats2half2_rn(xs[2], xs[3]);
    __half2 h2 = __floats2half2_rn(xs[4], 0.0f);
    __half2 h3 = __floats2half2_rn(0.0f, 0.0f);
    uint4 v;
    v.x = *(unsigned*)&h0; v.y = *(unsigned*)&h1;
    v.z = *(unsigned*)&h2; v.w = *(unsigned*)&h3;
    g_xh[n] = v;
}

// ---------------------------------------------------------------------------
// Zero deg + gsum
// ---------------------------------------------------------------------------
__global__ void zero_kernel() {
    int i = blockIdx.x * blockDim.x + threadIdx.x;
    if (i < N_NODES) g_deg[i] = 0;
    if (i < N_GRAPHS * HID) g_gsum[i] = 0.0f;
}

// ---------------------------------------------------------------------------
// Degree histogram over dst; atomic return value = edge's rank. 4 edges/thread.
// ---------------------------------------------------------------------------
__global__ void hist_kernel(const int* __restrict__ ei) {
    int t = blockIdx.x * blockDim.x + threadIdx.x;
    if (t >= N_EDGES / 4) return;
    int4 d4 = ((const int4*)(ei + N_EDGES))[t];
    int4 r;
    r.x = atomicAdd(&g_deg[d4.x], 1);
    r.y = atomicAdd(&g_deg[d4.y], 1);
    r.z = atomicAdd(&g_deg[d4.z], 1);
    r.w = atomicAdd(&g_deg[d4.w], 1);
    ((int4*)g_rank)[t] = r;
}

// ---------------------------------------------------------------------------
// Single-block exclusive scan of degrees -> offsets
// ---------------------------------------------------------------------------
__global__ void scan_kernel() {
    __shared__ int ssum[1024];
    int t = threadIdx.x;
    const int CH = (N_NODES + 1023) / 1024;  // 98
    int begin = t * CH; if (begin > N_NODES) begin = N_NODES;
    int end = begin + CH; if (end > N_NODES) end = N_NODES;
    int s = 0;
    for (int i = begin; i < end; ++i) s += g_deg[i];
    ssum[t] = s;
    __syncthreads();
    for (int d = 1; d < 1024; d <<= 1) {
        int v = (t >= d) ? ssum[t - d] : 0;
        __syncthreads();
        ssum[t] += v;
        __syncthreads();
    }
    int run = (t == 0) ? 0 : ssum[t - 1];
    for (int i = begin; i < end; ++i) {
        g_off[i] = run;
        run += g_deg[i];
    }
    if (t == 1023) g_off[N_NODES] = run;
}

// ---------------------------------------------------------------------------
// Scatter edges into CSR slots (no atomics). 4 edges/thread for MLP.
// ---------------------------------------------------------------------------
__global__ void scatter_kernel(const int* __restrict__ ei) {
    int t = blockIdx.x * blockDim.x + threadIdx.x;
    if (t >= N_EDGES / 4) return;
    int4 s4 = ((const int4*)ei)[t];
    int4 d4 = ((const int4*)(ei + N_EDGES))[t];
    int4 r4 = ((const int4*)g_rank)[t];
    int o0 = __ldg(&g_off[d4.x]);
    int o1 = __ldg(&g_off[d4.y]);
    int o2 = __ldg(&g_off[d4.z]);
    int o3 = __ldg(&g_off[d4.w]);
    g_srcs[o0 + r4.x] = s4.x;
    g_srcs[o1 + r4.y] = s4.y;
    g_srcs[o2 + r4.z] = s4.z;
    g_srcs[o3 + r4.w] = s4.w;
}

// ---------------------------------------------------------------------------
// Graph sizes via binary search (batch is sorted ascending)
// ---------------------------------------------------------------------------
__device__ __forceinline__ int lower_bound_batch(const int* b, int key) {
    int lo = 0, hi = N_NODES;
    while (lo < hi) {
        int mid = (lo + hi) >> 1;
        if (b[mid] < key) lo = mid + 1; else hi = mid;
    }
    return lo;
}
__global__ void count_kernel(const int* __restrict__ batch) {
    int g = blockIdx.x * blockDim.x + threadIdx.x;
    if (g >= N_GRAPHS) return;
    int a = lower_bound_batch(batch, g);
    int b = lower_bound_batch(batch, g + 1);
    g_gcnt[g] = (float)(b - a);
}

// ---------------------------------------------------------------------------
// Layer-1 gather-aggregate: z1[n] = x[n] + sum_{s in N(n)} x[s]  (5 feats)
// Warp per node; one 16B fp16 row load per edge per lane; fp32 accumulate.
// ---------------------------------------------------------------------------
__global__ void agg1_kernel(const float* __restrict__ x) {
    int gwarp = (blockIdx.x * blockDim.x + threadIdx.x) >> 5;
    int lane = threadIdx.x & 31;
    if (gwarp >= N_NODES) return;
    int start = g_off[gwarp], end = g_off[gwarp + 1];
    float a0 = 0, a1 = 0, a2 = 0, a3 = 0, a4 = 0;
    for (int e = start + lane; e < end; e += 32) {
        int s = g_srcs[e];
        uint4 v = g_xh[s];
        float2 p0 = __half22float2(*(__half2*)&v.x);
        float2 p1 = __half22float2(*(__half2*)&v.y);
        float2 p2 = __half22float2(*(__half2*)&v.z);
        a0 += p0.x; a1 += p0.y; a2 += p1.x; a3 += p1.y; a4 += p2.x;
    }
#pragma unroll
    for (int off = 16; off; off >>= 1) {
        a0 += __shfl_xor_sync(0xffffffffu, a0, off);
        a1 += __shfl_xor_sync(0xffffffffu, a1, off);
        a2 += __shfl_xor_sync(0xffffffffu, a2, off);
        a3 += __shfl_xor_sync(0xffffffffu, a3, off);
        a4 += __shfl_xor_sync(0xffffffffu, a4, off);
    }
    if (lane == 0) {
        const float* xn = x + gwarp * 5;
        float* z = g_z1 + gwarp * 5;
        z[0] = xn[0] + a0; z[1] = xn[1] + a1; z[2] = xn[2] + a2;
        z[3] = xn[3] + a3; z[4] = xn[4] + a4;
    }
}

// ---------------------------------------------------------------------------
// MLP1: h1 = relu( relu(z1 @ W1a + b1a) @ W1b + b1b ), output fp16.
// ---------------------------------------------------------------------------
#define NPB 128
__global__ __launch_bounds__(256) void mlp1_kernel(
    const float* __restrict__ W1a, const float* __restrict__ b1a,
    const float* __restrict__ W1b, const float* __restrict__ b1b) {
    __shared__ float sWa[5 * HID];
    __shared__ float sWb[HID * HID];
    __shared__ float sba[HID];
    __shared__ float sbb[HID];
    __shared__ float sz[4][5][8];
    __shared__ float st[4][HID][8];

    int j = threadIdx.x;
    int r = threadIdx.y;
    int tid = r * 64 + j;

    for (int i = tid; i < 5 * HID; i += 256) sWa[i] = W1a[i];
    for (int i = tid; i < HID * HID; i += 256) sWb[i] = W1b[i];
    if (tid < HID) sba[tid] = b1a[tid];
    else if (tid < 2 * HID) sbb[tid - HID] = b1b[tid - HID];
    __syncthreads();

    int base = blockIdx.x * NPB;
    for (int it = 0; it < NPB / 32; ++it) {
        int n0 = base + it * 32 + r * 8;
        if (j < 40) {
            int i = j & 7, k = j >> 3;
            int n = n0 + i;
            sz[r][k][i] = (n < N_NODES) ? g_z1[n * 5 + k] : 0.0f;
        }
        __syncthreads();
        float bias = sba[j];
        float a0 = bias, a1 = bias, a2 = bias, a3 = bias;
        float a4 = bias, a5 = bias, a6 = bias, a7 = bias;
#pragma unroll
        for (int k = 0; k < 5; ++k) {
            float w = sWa[k * HID + j];
            float4 za = *(const float4*)&sz[r][k][0];
            float4 zb = *(const float4*)&sz[r][k][4];
            a0 += za.x * w; a1 += za.y * w; a2 += za.z * w; a3 += za.w * w;
            a4 += zb.x * w; a5 += zb.y * w; a6 += zb.z * w; a7 += zb.w * w;
        }
        float4 ta, tb;
        ta.x = fmaxf(a0, 0.0f); ta.y = fmaxf(a1, 0.0f);
        ta.z = fmaxf(a2, 0.0f); ta.w = fmaxf(a3, 0.0f);
        tb.x = fmaxf(a4, 0.0f); tb.y = fmaxf(a5, 0.0f);
        tb.z = fmaxf(a6, 0.0f); tb.w = fmaxf(a7, 0.0f);
        *(float4*)&st[r][j][0] = ta;
        *(float4*)&st[r][j][4] = tb;
        __syncthreads();
        float bias2 = sbb[j];
        float b0 = bias2, b1 = bias2, b2 = bias2, b3 = bias2;
        float b4 = bias2, b5 = bias2, b6 = bias2, b7 = bias2;
#pragma unroll
        for (int k = 0; k < HID; ++k) {
            float w = sWb[k * HID + j];
            float4 za = *(const float4*)&st[r][k][0];
            float4 zb = *(const float4*)&st[r][k][4];
            b0 += za.x * w; b1 += za.y * w; b2 += za.z * w; b3 += za.w * w;
            b4 += zb.x * w; b5 += zb.y * w; b6 += zb.z * w; b7 += zb.w * w;
        }
        __half* h1 = (__half*)g_h1h;
        if (n0 + 0 < N_NODES) h1[(n0 + 0) * HID + j] = __float2half(fmaxf(b0, 0.0f));
        if (n0 + 1 < N_NODES) h1[(n0 + 1) * HID + j] = __float2half(fmaxf(b1, 0.0f));
        if (n0 + 2 < N_NODES) h1[(n0 + 2) * HID + j] = __float2half(fmaxf(b2, 0.0f));
        if (n0 + 3 < N_NODES) h1[(n0 + 3) * HID + j] = __float2half(fmaxf(b3, 0.0f));
        if (n0 + 4 < N_NODES) h1[(n0 + 4) * HID + j] = __float2half(fmaxf(b4, 0.0f));
        if (n0 + 5 < N_NODES) h1[(n0 + 5) * HID + j] = __float2half(fmaxf(b5, 0.0f));
        if (n0 + 6 < N_NODES) h1[(n0 + 6) * HID + j] = __float2half(fmaxf(b6, 0.0f));
        if (n0 + 7 < N_NODES) h1[(n0 + 7) * HID + j] = __float2half(fmaxf(b7, 0.0f));
        __syncthreads();
    }
}

// ---------------------------------------------------------------------------
// Layer-2 gather-aggregate (fp16 gather, fp32 accumulate), unrolled x2.
// ---------------------------------------------------------------------------
__global__ void agg2_kernel() {
    int gwarp = (blockIdx.x * blockDim.x + threadIdx.x) >> 5;
    int lane = threadIdx.x & 31;
    if (gwarp >= N_NODES) return;
    int start = g_off[gwarp], end = g_off[gwarp + 1];
    float a0 = 0.0f, a1 = 0.0f;
    for (int b = start; b < end; b += 32) {
        int m = end - b; if (m > 32) m = 32;
        int myS = (b + lane < end) ? g_srcs[b + lane] : 0;
        int i = 0;
        for (; i + 1 < m; i += 2) {
            int s0 = __shfl_sync(0xffffffffu, myS, i);
            int s1 = __shfl_sync(0xffffffffu, myS, i + 1);
            __half2 v0 = g_h1h[s0 * (HID/2) + lane];
            __half2 v1 = g_h1h[s1 * (HID/2) + lane];
            float2 f0 = __half22float2(v0);
            float2 f1 = __half22float2(v1);
            a0 += f0.x; a1 += f0.y;
            a0 += f1.x; a1 += f1.y;
        }
        if (i < m) {
            int s0 = __shfl_sync(0xffffffffu, myS, i);
            float2 f0 = __half22float2(g_h1h[s0 * (HID/2) + lane]);
            a0 += f0.x; a1 += f0.y;
        }
    }
    float2 hs = __half22float2(g_h1h[gwarp * (HID/2) + lane]);
    float2 z;
    z.x = hs.x + a0;
    z.y = hs.y + a1;
    ((float2*)g_z2)[gwarp * (HID/2) + lane] = z;
}

// ---------------------------------------------------------------------------
// MLP2 + fused mean-pool scatter
// ---------------------------------------------------------------------------
__global__ __launch_bounds__(256) void mlp2_kernel(
    const int* __restrict__ batch,
    const float* __restrict__ W2a, const float* __restrict__ b2a,
    const float* __restrict__ W2b, const float* __restrict__ b2b) {
    __shared__ float sWa[HID * HID];
    __shared__ float sWb[HID * HID];
    __shared__ float sba[HID];
    __shared__ float sbb[HID];
    __shared__ float sz[4][HID][8];
    __shared__ float st[4][HID][8];

    int j = threadIdx.x;
    int r = threadIdx.y;
    int tid = r * 64 + j;

    for (int i = tid; i < HID * HID; i += 256) {
        sWa[i] = W2a[i];
        sWb[i] = W2b[i];
    }
    if (tid < HID) sba[tid] = b2a[tid];
    else if (tid < 2 * HID) sbb[tid - HID] = b2b[tid - HID];
    __syncthreads();

    int base = blockIdx.x * NPB;
    for (int it = 0; it < NPB / 32; ++it) {
        int n0 = base + it * 32 + r * 8;
#pragma unroll
        for (int i = 0; i < 8; ++i) {
            int n = n0 + i;
            sz[r][j][i] = (n < N_NODES) ? g_z2[n * HID + j] : 0.0f;
        }
        __syncthreads();
        float bias = sba[j];
        float a0 = bias, a1 = bias, a2 = bias, a3 = bias;
        float a4 = bias, a5 = bias, a6 = bias, a7 = bias;
#pragma unroll
        for (int k = 0; k < HID; ++k) {
            float w = sWa[k * HID + j];
            float4 za = *(const float4*)&sz[r][k][0];
            float4 zb = *(const float4*)&sz[r][k][4];
            a0 += za.x * w; a1 += za.y * w; a2 += za.z * w; a3 += za.w * w;
            a4 += zb.x * w; a5 += zb.y * w; a6 += zb.z * w; a7 += zb.w * w;
        }
        float4 ta, tb;
        ta.x = fmaxf(a0, 0.0f); ta.y = fmaxf(a1, 0.0f);
        ta.z = fmaxf(a2, 0.0f); ta.w = fmaxf(a3, 0.0f);
        tb.x = fmaxf(a4, 0.0f); tb.y = fmaxf(a5, 0.0f);
        tb.z = fmaxf(a6, 0.0f); tb.w = fmaxf(a7, 0.0f);
        *(float4*)&st[r][j][0] = ta;
        *(float4*)&st[r][j][4] = tb;
        __syncthreads();
        float bias2 = sbb[j];
        float b0 = bias2, b1 = bias2, b2 = bias2, b3 = bias2;
        float b4 = bias2, b5 = bias2, b6 = bias2, b7 = bias2;
#pragma unroll
        for (int k = 0; k < HID; ++k) {
            float w = sWb[k * HID + j];
            float4 za = *(const float4*)&st[r][k][0];
            float4 zb = *(const float4*)&st[r][k][4];
            b0 += za.x * w; b1 += za.y * w; b2 += za.z * w; b3 += za.w * w;
            b4 += zb.x * w; b5 += zb.y * w; b6 += zb.z * w; b7 += zb.w * w;
        }
        if (n0 + 0 < N_NODES) atomicAdd(&g_gsum[batch[n0 + 0] * HID + j], fmaxf(b0, 0.0f));
        if (n0 + 1 < N_NODES) atomicAdd(&g_gsum[batch[n0 + 1] * HID + j], fmaxf(b1, 0.0f));
        if (n0 + 2 < N_NODES) atomicAdd(&g_gsum[batch[n0 + 2] * HID + j], fmaxf(b2, 0.0f));
        if (n0 + 3 < N_NODES) atomicAdd(&g_gsum[batch[n0 + 3] * HID + j], fmaxf(b3, 0.0f));
        if (n0 + 4 < N_NODES) atomicAdd(&g_gsum[batch[n0 + 4] * HID + j], fmaxf(b4, 0.0f));
        if (n0 + 5 < N_NODES) atomicAdd(&g_gsum[batch[n0 + 5] * HID + j], fmaxf(b5, 0.0f));
        if (n0 + 6 < N_NODES) atomicAdd(&g_gsum[batch[n0 + 6] * HID + j], fmaxf(b6, 0.0f));
        if (n0 + 7 < N_NODES) atomicAdd(&g_gsum[batch[n0 + 7] * HID + j], fmaxf(b7, 0.0f));
        __syncthreads();
    }
}

// ---------------------------------------------------------------------------
// Head: out[g] = (gsum[g] / max(cnt,1)) @ Wc + bc
// ---------------------------------------------------------------------------
__global__ void head_kernel(const float* __restrict__ Wc,
                            const float* __restrict__ bc,
                            float* __restrict__ out) {
    int g = blockIdx.x * blockDim.x + threadIdx.x;
    if (g >= N_GRAPHS) return;
    float inv = 1.0f / fmaxf(g_gcnt[g], 1.0f);
    float a0 = bc[0], a1 = bc[1];
#pragma unroll
    for (int jj = 0; jj < HID; ++jj) {
        float p = g_gsum[g * HID + jj] * inv;
        a0 += p * Wc[jj * 2 + 0];
        a1 += p * Wc[jj * 2 + 1];
    }
    out[g * 2 + 0] = a0;
    out[g * 2 + 1] = a1;
}

// ---------------------------------------------------------------------------
extern "C" void kernel_launch(void* const* d_in, const int* in_sizes, int n_in,
                              void* d_out, int out_size) {
    const float* x   = (const float*)d_in[0];
    const int*   ei  = (const int*)d_in[1];
    const int*   bat = (const int*)d_in[2];
    const float* W1a = (const float*)d_in[3];
    const float* b1a = (const float*)d_in[4];
    const float* W1b = (const float*)d_in[5];
    const float* b1b = (const float*)d_in[6];
    const float* W2a = (const float*)d_in[7];
    const float* b2a = (const float*)d_in[8];
    const float* W2b = (const float*)d_in[9];
    const float* b2b = (const float*)d_in[10];
    const float* Wc  = (const float*)d_in[11];
    const float* bc  = (const float*)d_in[12];
    float* out = (float*)d_out;

    xprep_kernel<<<(N_NODES + 255) / 256, 256>>>(x);
    zero_kernel<<<(N_NODES + 255) / 256, 256>>>();
    hist_kernel<<<(N_EDGES / 4 + 255) / 256, 256>>>(ei);
    scan_kernel<<<1, 1024>>>();
    scatter_kernel<<<(N_EDGES / 4 + 255) / 256, 256>>>(ei);
    count_kernel<<<(N_GRAPHS + 255) / 256, 256>>>(bat);

    // layer 1
    agg1_kernel<<<(N_NODES * 32 + 255) / 256, 256>>>(x);
    mlp1_kernel<<<(N_NODES + NPB - 1) / NPB, dim3(64, 4)>>>(W1a, b1a, W1b, b1b);

    // layer 2
    agg2_kernel<<<(N_NODES * 32 + 255) / 256, 256>>>();
    mlp2_kernel<<<(N_NODES + NPB - 1) / NPB, dim3(64, 4)>>>(bat, W2a, b2a, W2b, b2b);

    head_kernel<<<(N_GRAPHS + 255) / 256, 256>>>(Wc, bc, out);
}

// round 7
// speedup vs baseline: 1.3031x; 1.3031x over previous
#include <cuda_runtime.h>
#include <cuda_fp16.h>
#include <cstdint>

#define N_NODES 100000
#define N_EDGES 3200000
#define N_GRAPHS 1024
#define HID 64

#define SCAN_BLOCKS 98   // ceil(100000 / 1024)
#define PREP_THREADS (N_NODES + 4)   // covers g_deg pad; > N_GRAPHS*HID too? no: 65536 < 100004, ok max is 100004

// ---------------------------------------------------------------------------
// Scratch (device globals; no allocations allowed)
// ---------------------------------------------------------------------------
__device__ int     g_deg[N_NODES + 4];       // +pad so int4 tail loads are safe
__device__ int     g_off[N_NODES + 1];
__device__ int     g_rank[N_EDGES];          // per-edge rank within its dst bucket
__device__ int     g_srcs[N_EDGES];          // src ids grouped by dst (CSR)
__device__ int     g_bsum[SCAN_BLOCKS];
__device__ int     g_boff[SCAN_BLOCKS];
__device__ uint4   g_xh[N_NODES];            // x padded to 8 halfs (16B/node)
__device__ float   g_z1[N_NODES * 5];        // x + agg1
__device__ __half2 g_h1h[N_NODES * (HID/2)]; // layer-1 output (fp16)
__device__ float   g_z2[N_NODES * HID];      // h1 + agg2 (fp32)
__device__ float   g_gsum[N_GRAPHS * HID];
__device__ float   g_gcnt[N_GRAPHS];

// ---------------------------------------------------------------------------
// Pack x into fp16 [N][8] rows + zero deg/gsum (fused housekeeping).
// Grid must cover max(N_NODES+4, N_GRAPHS*HID) threads.
// ---------------------------------------------------------------------------
__global__ void prep_kernel(const float* __restrict__ x) {
    int n = blockIdx.x * blockDim.x + threadIdx.x;
    if (n < N_NODES) {
        const float* xs = x + n * 5;
        __half2 h0 = __floats2half2_rn(xs[0], xs[1]);
        __half2 h1 = __floats2half2_rn(xs[2], xs[3]);
        __half2 h2 = __floats2half2_rn(xs[4], 0.0f);
        __half2 h3 = __floats2half2_rn(0.0f, 0.0f);
        uint4 v;
        v.x = *(unsigned*)&h0; v.y = *(unsigned*)&h1;
        v.z = *(unsigned*)&h2; v.w = *(unsigned*)&h3;
        g_xh[n] = v;
    }
    if (n < N_NODES + 4) g_deg[n] = 0;
    if (n < N_GRAPHS * HID) g_gsum[n] = 0.0f;
}

// ---------------------------------------------------------------------------
// Degree histogram over dst; atomic return value = edge's rank. 4 edges/thread.
// ---------------------------------------------------------------------------
__global__ void hist_kernel(const int* __restrict__ ei) {
    int t = blockIdx.x * blockDim.x + threadIdx.x;
    if (t >= N_EDGES / 4) return;
    int4 d4 = ((const int4*)(ei + N_EDGES))[t];
    int4 r;
    r.x = atomicAdd(&g_deg[d4.x], 1);
    r.y = atomicAdd(&g_deg[d4.y], 1);
    r.z = atomicAdd(&g_deg[d4.z], 1);
    r.w = atomicAdd(&g_deg[d4.w], 1);
    ((int4*)g_rank)[t] = r;
}

// ---------------------------------------------------------------------------
// Multi-block exclusive scan of degrees -> offsets.
// Phase A: per-block sums (1024 nodes/block).
// ---------------------------------------------------------------------------
__global__ void scanA_kernel() {
    __shared__ int wsum[8];
    int t = threadIdx.x;
    int n0 = blockIdx.x * 1024 + t * 4;
    int s = 0;
    if (n0 + 3 < N_NODES) {
        int4 v = *(const int4*)&g_deg[n0];
        s = v.x + v.y + v.z + v.w;
    } else {
#pragma unroll
        for (int i = 0; i < 4; ++i)
            if (n0 + i < N_NODES) s += g_deg[n0 + i];
    }
    int lane = t & 31;
#pragma unroll
    for (int off = 16; off; off >>= 1) s += __shfl_xor_sync(0xffffffffu, s, off);
    if (lane == 0) wsum[t >> 5] = s;
    __syncthreads();
    if (t < 8) {
        int v = wsum[t];
#pragma unroll
        for (int off = 4; off; off >>= 1) v += __shfl_xor_sync(0xffu, v, off);
        if (t == 0) g_bsum[blockIdx.x] = v;
    }
}

// ---------------------------------------------------------------------------
// Phase B: single small block scans the 98 block sums (exclusive).
// ---------------------------------------------------------------------------
__global__ void scanB_kernel() {
    __shared__ int ss[128];
    int t = threadIdx.x;
    int v = (t < SCAN_BLOCKS) ? g_bsum[t] : 0;
    ss[t] = v;
    __syncthreads();
    for (int d = 1; d < 128; d <<= 1) {
        int u = (t >= d) ? ss[t - d] : 0;
        __syncthreads();
        ss[t] += u;
        __syncthreads();
    }
    if (t < SCAN_BLOCKS) g_boff[t] = ss[t] - v;
    if (t == SCAN_BLOCKS - 1) g_off[N_NODES] = ss[t];
}

// ---------------------------------------------------------------------------
// Phase C: per-block local exclusive scan + block offset -> g_off.
// ---------------------------------------------------------------------------
__global__ void scanC_kernel() {
    __shared__ int ssum[256];
    int t = threadIdx.x;
    int n0 = blockIdx.x * 1024 + t * 4;
    int v0 = 0, v1 = 0, v2 = 0, v3 = 0;
    if (n0 + 3 < N_NODES) {
        int4 v = *(const int4*)&g_deg[n0];
        v0 = v.x; v1 = v.y; v2 = v.z; v3 = v.w;
    } else {
        if (n0 + 0 < N_NODES) v0 = g_deg[n0 + 0];
        if (n0 + 1 < N_NODES) v1 = g_deg[n0 + 1];
        if (n0 + 2 < N_NODES) v2 = g_deg[n0 + 2];
        if (n0 + 3 < N_NODES) v3 = g_deg[n0 + 3];
    }
    int s = v0 + v1 + v2 + v3;
    ssum[t] = s;
    __syncthreads();
    for (int d = 1; d < 256; d <<= 1) {
        int u = (t >= d) ? ssum[t - d] : 0;
        __syncthreads();
        ssum[t] += u;
        __syncthreads();
    }
    int prefix = g_boff[blockIdx.x] + ssum[t] - s;  // exclusive for this thread
    if (n0 + 0 < N_NODES) { g_off[n0 + 0] = prefix; prefix += v0; }
    if (n0 + 1 < N_NODES) { g_off[n0 + 1] = prefix; prefix += v1; }
    if (n0 + 2 < N_NODES) { g_off[n0 + 2] = prefix; prefix += v2; }
    if (n0 + 3 < N_NODES) { g_off[n0 + 3] = prefix; }
}

// ---------------------------------------------------------------------------
// Scatter edges into CSR slots (no atomics). 4 edges/thread for MLP.
// ---------------------------------------------------------------------------
__global__ void scatter_kernel(const int* __restrict__ ei) {
    int t = blockIdx.x * blockDim.x + threadIdx.x;
    if (t >= N_EDGES / 4) return;
    int4 s4 = ((const int4*)ei)[t];
    int4 d4 = ((const int4*)(ei + N_EDGES))[t];
    int4 r4 = ((const int4*)g_rank)[t];
    int o0 = __ldg(&g_off[d4.x]);
    int o1 = __ldg(&g_off[d4.y]);
    int o2 = __ldg(&g_off[d4.z]);
    int o3 = __ldg(&g_off[d4.w]);
    g_srcs[o0 + r4.x] = s4.x;
    g_srcs[o1 + r4.y] = s4.y;
    g_srcs[o2 + r4.z] = s4.z;
    g_srcs[o3 + r4.w] = s4.w;
}

// ---------------------------------------------------------------------------
// Graph sizes via binary search (batch is sorted ascending)
// ---------------------------------------------------------------------------
__device__ __forceinline__ int lower_bound_batch(const int* b, int key) {
    int lo = 0, hi = N_NODES;
    while (lo < hi) {
        int mid = (lo + hi) >> 1;
        if (b[mid] < key) lo = mid + 1; else hi = mid;
    }
    return lo;
}
__global__ void count_kernel(const int* __restrict__ batch) {
    int g = blockIdx.x * blockDim.x + threadIdx.x;
    if (g >= N_GRAPHS) return;
    int a = lower_bound_batch(batch, g);
    int b = lower_bound_batch(batch, g + 1);
    g_gcnt[g] = (float)(b - a);
}

// ---------------------------------------------------------------------------
// Layer-1 gather-aggregate: z1[n] = x[n] + sum_{s in N(n)} x[s]  (5 feats)
// ---------------------------------------------------------------------------
__global__ void agg1_kernel(const float* __restrict__ x) {
    int gwarp = (blockIdx.x * blockDim.x + threadIdx.x) >> 5;
    int lane = threadIdx.x & 31;
    if (gwarp >= N_NODES) return;
    int start = g_off[gwarp], end = g_off[gwarp + 1];
    float a0 = 0, a1 = 0, a2 = 0, a3 = 0, a4 = 0;
    for (int e = start + lane; e < end; e += 32) {
        int s = g_srcs[e];
        uint4 v = g_xh[s];
        float2 p0 = __half22float2(*(__half2*)&v.x);
        float2 p1 = __half22float2(*(__half2*)&v.y);
        float2 p2 = __half22float2(*(__half2*)&v.z);
        a0 += p0.x; a1 += p0.y; a2 += p1.x; a3 += p1.y; a4 += p2.x;
    }
#pragma unroll
    for (int off = 16; off; off >>= 1) {
        a0 += __shfl_xor_sync(0xffffffffu, a0, off);
        a1 += __shfl_xor_sync(0xffffffffu, a1, off);
        a2 += __shfl_xor_sync(0xffffffffu, a2, off);
        a3 += __shfl_xor_sync(0xffffffffu, a3, off);
        a4 += __shfl_xor_sync(0xffffffffu, a4, off);
    }
    if (lane == 0) {
        const float* xn = x + gwarp * 5;
        float* z = g_z1 + gwarp * 5;
        z[0] = xn[0] + a0; z[1] = xn[1] + a1; z[2] = xn[2] + a2;
        z[3] = xn[3] + a3; z[4] = xn[4] + a4;
    }
}

// ---------------------------------------------------------------------------
// MLP1: h1 = relu( relu(z1 @ W1a + b1a) @ W1b + b1b ), output fp16.
// ---------------------------------------------------------------------------
#define NPB 128
__global__ __launch_bounds__(256) void mlp1_kernel(
    const float* __restrict__ W1a, const float* __restrict__ b1a,
    const float* __restrict__ W1b, const float* __restrict__ b1b) {
    __shared__ float sWa[5 * HID];
    __shared__ float sWb[HID * HID];
    __shared__ float sba[HID];
    __shared__ float sbb[HID];
    __shared__ float sz[4][5][8];
    __shared__ float st[4][HID][8];

    int j = threadIdx.x;
    int r = threadIdx.y;
    int tid = r * 64 + j;

    for (int i = tid; i < 5 * HID; i += 256) sWa[i] = W1a[i];
    for (int i = tid; i < HID * HID; i += 256) sWb[i] = W1b[i];
    if (tid < HID) sba[tid] = b1a[tid];
    else if (tid < 2 * HID) sbb[tid - HID] = b1b[tid - HID];
    __syncthreads();

    int base = blockIdx.x * NPB;
    for (int it = 0; it < NPB / 32; ++it) {
        int n0 = base + it * 32 + r * 8;
        if (j < 40) {
            int i = j & 7, k = j >> 3;
            int n = n0 + i;
            sz[r][k][i] = (n < N_NODES) ? g_z1[n * 5 + k] : 0.0f;
        }
        __syncthreads();
        float bias = sba[j];
        float a0 = bias, a1 = bias, a2 = bias, a3 = bias;
        float a4 = bias, a5 = bias, a6 = bias, a7 = bias;
#pragma unroll
        for (int k = 0; k < 5; ++k) {
            float w = sWa[k * HID + j];
            float4 za = *(const float4*)&sz[r][k][0];
            float4 zb = *(const float4*)&sz[r][k][4];
            a0 += za.x * w; a1 += za.y * w; a2 += za.z * w; a3 += za.w * w;
            a4 += zb.x * w; a5 += zb.y * w; a6 += zb.z * w; a7 += zb.w * w;
        }
        float4 ta, tb;
        ta.x = fmaxf(a0, 0.0f); ta.y = fmaxf(a1, 0.0f);
        ta.z = fmaxf(a2, 0.0f); ta.w = fmaxf(a3, 0.0f);
        tb.x = fmaxf(a4, 0.0f); tb.y = fmaxf(a5, 0.0f);
        tb.z = fmaxf(a6, 0.0f); tb.w = fmaxf(a7, 0.0f);
        *(float4*)&st[r][j][0] = ta;
        *(float4*)&st[r][j][4] = tb;
        __syncthreads();
        float bias2 = sbb[j];
        float b0 = bias2, b1 = bias2, b2 = bias2, b3 = bias2;
        float b4 = bias2, b5 = bias2, b6 = bias2, b7 = bias2;
#pragma unroll
        for (int k = 0; k < HID; ++k) {
            float w = sWb[k * HID + j];
            float4 za = *(const float4*)&st[r][k][0];
            float4 zb = *(const float4*)&st[r][k][4];
            b0 += za.x * w; b1 += za.y * w; b2 += za.z * w; b3 += za.w * w;
            b4 += zb.x * w; b5 += zb.y * w; b6 += zb.z * w; b7 += zb.w * w;
        }
        __half* h1 = (__half*)g_h1h;
        if (n0 + 0 < N_NODES) h1[(n0 + 0) * HID + j] = __float2half(fmaxf(b0, 0.0f));
        if (n0 + 1 < N_NODES) h1[(n0 + 1) * HID + j] = __float2half(fmaxf(b1, 0.0f));
        if (n0 + 2 < N_NODES) h1[(n0 + 2) * HID + j] = __float2half(fmaxf(b2, 0.0f));
        if (n0 + 3 < N_NODES) h1[(n0 + 3) * HID + j] = __float2half(fmaxf(b3, 0.0f));
        if (n0 + 4 < N_NODES) h1[(n0 + 4) * HID + j] = __float2half(fmaxf(b4, 0.0f));
        if (n0 + 5 < N_NODES) h1[(n0 + 5) * HID + j] = __float2half(fmaxf(b5, 0.0f));
        if (n0 + 6 < N_NODES) h1[(n0 + 6) * HID + j] = __float2half(fmaxf(b6, 0.0f));
        if (n0 + 7 < N_NODES) h1[(n0 + 7) * HID + j] = __float2half(fmaxf(b7, 0.0f));
        __syncthreads();
    }
}

// ---------------------------------------------------------------------------
// Layer-2 gather-aggregate (fp16 gather, fp32 accumulate), unrolled x2.
// ---------------------------------------------------------------------------
__global__ void agg2_kernel() {
    int gwarp = (blockIdx.x * blockDim.x + threadIdx.x) >> 5;
    int lane = threadIdx.x & 31;
    if (gwarp >= N_NODES) return;
    int start = g_off[gwarp], end = g_off[gwarp + 1];
    float a0 = 0.0f, a1 = 0.0f;
    for (int b = start; b < end; b += 32) {
        int m = end - b; if (m > 32) m = 32;
        int myS = (b + lane < end) ? g_srcs[b + lane] : 0;
        int i = 0;
        for (; i + 1 < m; i += 2) {
            int s0 = __shfl_sync(0xffffffffu, myS, i);
            int s1 = __shfl_sync(0xffffffffu, myS, i + 1);
            __half2 v0 = g_h1h[s0 * (HID/2) + lane];
            __half2 v1 = g_h1h[s1 * (HID/2) + lane];
            float2 f0 = __half22float2(v0);
            float2 f1 = __half22float2(v1);
            a0 += f0.x; a1 += f0.y;
            a0 += f1.x; a1 += f1.y;
        }
        if (i < m) {
            int s0 = __shfl_sync(0xffffffffu, myS, i);
            float2 f0 = __half22float2(g_h1h[s0 * (HID/2) + lane]);
            a0 += f0.x; a1 += f0.y;
        }
    }
    float2 hs = __half22float2(g_h1h[gwarp * (HID/2) + lane]);
    float2 z;
    z.x = hs.x + a0;
    z.y = hs.y + a1;
    ((float2*)g_z2)[gwarp * (HID/2) + lane] = z;
}

// ---------------------------------------------------------------------------
// MLP2 + fused mean-pool scatter
// ---------------------------------------------------------------------------
__global__ __launch_bounds__(256) void mlp2_kernel(
    const int* __restrict__ batch,
    const float* __restrict__ W2a, const float* __restrict__ b2a,
    const float* __restrict__ W2b, const float* __restrict__ b2b) {
    __shared__ float sWa[HID * HID];
    __shared__ float sWb[HID * HID];
    __shared__ float sba[HID];
    __shared__ float sbb[HID];
    __shared__ float sz[4][HID][8];
    __shared__ float st[4][HID][8];

    int j = threadIdx.x;
    int r = threadIdx.y;
    int tid = r * 64 + j;

    for (int i = tid; i < HID * HID; i += 256) {
        sWa[i] = W2a[i];
        sWb[i] = W2b[i];
    }
    if (tid < HID) sba[tid] = b2a[tid];
    else if (tid < 2 * HID) sbb[tid - HID] = b2b[tid - HID];
    __syncthreads();

    int base = blockIdx.x * NPB;
    for (int it = 0; it < NPB / 32; ++it) {
        int n0 = base + it * 32 + r * 8;
#pragma unroll
        for (int i = 0; i < 8; ++i) {
            int n = n0 + i;
            sz[r][j][i] = (n < N_NODES) ? g_z2[n * HID + j] : 0.0f;
        }
        __syncthreads();
        float bias = sba[j];
        float a0 = bias, a1 = bias, a2 = bias, a3 = bias;
        float a4 = bias, a5 = bias, a6 = bias, a7 = bias;
#pragma unroll
        for (int k = 0; k < HID; ++k) {
            float w = sWa[k * HID + j];
            float4 za = *(const float4*)&sz[r][k][0];
            float4 zb = *(const float4*)&sz[r][k][4];
            a0 += za.x * w; a1 += za.y * w; a2 += za.z * w; a3 += za.w * w;
            a4 += zb.x * w; a5 += zb.y * w; a6 += zb.z * w; a7 += zb.w * w;
        }
        float4 ta, tb;
        ta.x = fmaxf(a0, 0.0f); ta.y = fmaxf(a1, 0.0f);
        ta.z = fmaxf(a2, 0.0f); ta.w = fmaxf(a3, 0.0f);
        tb.x = fmaxf(a4, 0.0f); tb.y = fmaxf(a5, 0.0f);
        tb.z = fmaxf(a6, 0.0f); tb.w = fmaxf(a7, 0.0f);
        *(float4*)&st[r][j][0] = ta;
        *(float4*)&st[r][j][4] = tb;
        __syncthreads();
        float bias2 = sbb[j];
        float b0 = bias2, b1 = bias2, b2 = bias2, b3 = bias2;
        float b4 = bias2, b5 = bias2, b6 = bias2, b7 = bias2;
#pragma unroll
        for (int k = 0; k < HID; ++k) {
            float w = sWb[k * HID + j];
            float4 za = *(const float4*)&st[r][k][0];
            float4 zb = *(const float4*)&st[r][k][4];
            b0 += za.x * w; b1 += za.y * w; b2 += za.z * w; b3 += za.w * w;
            b4 += zb.x * w; b5 += zb.y * w; b6 += zb.z * w; b7 += zb.w * w;
        }
        if (n0 + 0 < N_NODES) atomicAdd(&g_gsum[batch[n0 + 0] * HID + j], fmaxf(b0, 0.0f));
        if (n0 + 1 < N_NODES) atomicAdd(&g_gsum[batch[n0 + 1] * HID + j], fmaxf(b1, 0.0f));
        if (n0 + 2 < N_NODES) atomicAdd(&g_gsum[batch[n0 + 2] * HID + j], fmaxf(b2, 0.0f));
        if (n0 + 3 < N_NODES) atomicAdd(&g_gsum[batch[n0 + 3] * HID + j], fmaxf(b3, 0.0f));
        if (n0 + 4 < N_NODES) atomicAdd(&g_gsum[batch[n0 + 4] * HID + j], fmaxf(b4, 0.0f));
        if (n0 + 5 < N_NODES) atomicAdd(&g_gsum[batch[n0 + 5] * HID + j], fmaxf(b5, 0.0f));
        if (n0 + 6 < N_NODES) atomicAdd(&g_gsum[batch[n0 + 6] * HID + j], fmaxf(b6, 0.0f));
        if (n0 + 7 < N_NODES) atomicAdd(&g_gsum[batch[n0 + 7] * HID + j], fmaxf(b7, 0.0f));
        __syncthreads();
    }
}

// ---------------------------------------------------------------------------
// Head: out[g] = (gsum[g] / max(cnt,1)) @ Wc + bc
// ---------------------------------------------------------------------------
__global__ void head_kernel(const float* __restrict__ Wc,
                            const float* __restrict__ bc,
                            float* __restrict__ out) {
    int g = blockIdx.x * blockDim.x + threadIdx.x;
    if (g >= N_GRAPHS) return;
    float inv = 1.0f / fmaxf(g_gcnt[g], 1.0f);
    float a0 = bc[0], a1 = bc[1];
#pragma unroll
    for (int jj = 0; jj < HID; ++jj) {
        float p = g_gsum[g * HID + jj] * inv;
        a0 += p * Wc[jj * 2 + 0];
        a1 += p * Wc[jj * 2 + 1];
    }
    out[g * 2 + 0] = a0;
    out[g * 2 + 1] = a1;
}

// ---------------------------------------------------------------------------
extern "C" void kernel_launch(void* const* d_in, const int* in_sizes, int n_in,
                              void* d_out, int out_size) {
    const float* x   = (const float*)d_in[0];
    const int*   ei  = (const int*)d_in[1];
    const int*   bat = (const int*)d_in[2];
    const float* W1a = (const float*)d_in[3];
    const float* b1a = (const float*)d_in[4];
    const float* W1b = (const float*)d_in[5];
    const float* b1b = (const float*)d_in[6];
    const float* W2a = (const float*)d_in[7];
    const float* b2a = (const float*)d_in[8];
    const float* W2b = (const float*)d_in[9];
    const float* b2b = (const float*)d_in[10];
    const float* Wc  = (const float*)d_in[11];
    const float* bc  = (const float*)d_in[12];
    float* out = (float*)d_out;

    // grid covers max(N_NODES+4, N_GRAPHS*HID) = 100004 elements
    prep_kernel<<<(N_NODES + 4 + 255) / 256, 256>>>(x);
    hist_kernel<<<(N_EDGES / 4 + 255) / 256, 256>>>(ei);
    scanA_kernel<<<SCAN_BLOCKS, 256>>>();
    scanB_kernel<<<1, 128>>>();
    scanC_kernel<<<SCAN_BLOCKS, 256>>>();
    scatter_kernel<<<(N_EDGES / 4 + 255) / 256, 256>>>(ei);
    count_kernel<<<(N_GRAPHS + 255) / 256, 256>>>(bat);

    // layer 1
    agg1_kernel<<<(N_NODES * 32 + 255) / 256, 256>>>(x);
    mlp1_kernel<<<(N_NODES + NPB - 1) / NPB, dim3(64, 4)>>>(W1a, b1a, W1b, b1b);

    // layer 2
    agg2_kernel<<<(N_NODES * 32 + 255) / 256, 256>>>();
    mlp2_kernel<<<(N_NODES + NPB - 1) / NPB, dim3(64, 4)>>>(bat, W2a, b2a, W2b, b2b);

    head_kernel<<<(N_GRAPHS + 255) / 256, 256>>>(Wc, bc, out);
}

// round 8
// speedup vs baseline: 1.6859x; 1.2938x over previous
#include <cuda_runtime.h>
#include <cuda_fp16.h>
#include <cstdint>

#define N_NODES 100000
#define N_EDGES 3200000
#define N_GRAPHS 1024
#define HID 64

#define SCAN_BLOCKS 98   // ceil(100000 / 1024)
#define WARP_TILES 6250  // 100000 / 16 (exact)

// ---------------------------------------------------------------------------
// Scratch (device globals; no allocations allowed)
// ---------------------------------------------------------------------------
__device__ int     g_deg[N_NODES + 4];       // +pad so int4 tail loads are safe
__device__ int     g_off[N_NODES + 1];
__device__ int     g_rank[N_EDGES];
__device__ int     g_srcs[N_EDGES];
__device__ int     g_bsum[SCAN_BLOCKS];
__device__ int     g_boff[SCAN_BLOCKS];
__device__ uint4   g_xh[N_NODES];            // x padded to 8 halfs
__device__ float   g_z1[N_NODES * 5];
__device__ __half2 g_h1h[N_NODES * (HID/2)]; // layer-1 output (fp16)
__device__ __half2 g_z2h[N_NODES * (HID/2)]; // h1 + agg2 (fp16)
__device__ float   g_gsum[N_GRAPHS * HID];
__device__ float   g_gcnt[N_GRAPHS];

// ---------------------------------------------------------------------------
// Pack x into fp16 rows + zero deg/gsum. Grid covers N_NODES+4 threads.
// ---------------------------------------------------------------------------
__global__ void prep_kernel(const float* __restrict__ x) {
    int n = blockIdx.x * blockDim.x + threadIdx.x;
    if (n < N_NODES) {
        const float* xs = x + n * 5;
        __half2 h0 = __floats2half2_rn(xs[0], xs[1]);
        __half2 h1 = __floats2half2_rn(xs[2], xs[3]);
        __half2 h2 = __floats2half2_rn(xs[4], 0.0f);
        __half2 h3 = __floats2half2_rn(0.0f, 0.0f);
        uint4 v;
        v.x = *(unsigned*)&h0; v.y = *(unsigned*)&h1;
        v.z = *(unsigned*)&h2; v.w = *(unsigned*)&h3;
        g_xh[n] = v;
    }
    if (n < N_NODES + 4) g_deg[n] = 0;
    if (n < N_GRAPHS * HID) g_gsum[n] = 0.0f;
}

// ---------------------------------------------------------------------------
// Degree histogram (rank capture), 4 edges/thread.
// ---------------------------------------------------------------------------
__global__ void hist_kernel(const int* __restrict__ ei) {
    int t = blockIdx.x * blockDim.x + threadIdx.x;
    if (t >= N_EDGES / 4) return;
    int4 d4 = ((const int4*)(ei + N_EDGES))[t];
    int4 r;
    r.x = atomicAdd(&g_deg[d4.x], 1);
    r.y = atomicAdd(&g_deg[d4.y], 1);
    r.z = atomicAdd(&g_deg[d4.z], 1);
    r.w = atomicAdd(&g_deg[d4.w], 1);
    ((int4*)g_rank)[t] = r;
}

// ---------------------------------------------------------------------------
// Multi-block exclusive scan: A (block sums), B (scan sums), C (final).
// ---------------------------------------------------------------------------
__global__ void scanA_kernel() {
    __shared__ int wsum[8];
    int t = threadIdx.x;
    int n0 = blockIdx.x * 1024 + t * 4;
    int s = 0;
    if (n0 + 3 < N_NODES) {
        int4 v = *(const int4*)&g_deg[n0];
        s = v.x + v.y + v.z + v.w;
    } else {
#pragma unroll
        for (int i = 0; i < 4; ++i)
            if (n0 + i < N_NODES) s += g_deg[n0 + i];
    }
    int lane = t & 31;
#pragma unroll
    for (int off = 16; off; off >>= 1) s += __shfl_xor_sync(0xffffffffu, s, off);
    if (lane == 0) wsum[t >> 5] = s;
    __syncthreads();
    if (t < 8) {
        int v = wsum[t];
#pragma unroll
        for (int off = 4; off; off >>= 1) v += __shfl_xor_sync(0xffu, v, off);
        if (t == 0) g_bsum[blockIdx.x] = v;
    }
}

__global__ void scanB_kernel() {
    __shared__ int ss[128];
    int t = threadIdx.x;
    int v = (t < SCAN_BLOCKS) ? g_bsum[t] : 0;
    ss[t] = v;
    __syncthreads();
    for (int d = 1; d < 128; d <<= 1) {
        int u = (t >= d) ? ss[t - d] : 0;
        __syncthreads();
        ss[t] += u;
        __syncthreads();
    }
    if (t < SCAN_BLOCKS) g_boff[t] = ss[t] - v;
    if (t == SCAN_BLOCKS - 1) g_off[N_NODES] = ss[t];
}

__global__ void scanC_kernel() {
    __shared__ int ssum[256];
    int t = threadIdx.x;
    int n0 = blockIdx.x * 1024 + t * 4;
    int v0 = 0, v1 = 0, v2 = 0, v3 = 0;
    if (n0 + 3 < N_NODES) {
        int4 v = *(const int4*)&g_deg[n0];
        v0 = v.x; v1 = v.y; v2 = v.z; v3 = v.w;
    } else {
        if (n0 + 0 < N_NODES) v0 = g_deg[n0 + 0];
        if (n0 + 1 < N_NODES) v1 = g_deg[n0 + 1];
        if (n0 + 2 < N_NODES) v2 = g_deg[n0 + 2];
        if (n0 + 3 < N_NODES) v3 = g_deg[n0 + 3];
    }
    int s = v0 + v1 + v2 + v3;
    ssum[t] = s;
    __syncthreads();
    for (int d = 1; d < 256; d <<= 1) {
        int u = (t >= d) ? ssum[t - d] : 0;
        __syncthreads();
        ssum[t] += u;
        __syncthreads();
    }
    int prefix = g_boff[blockIdx.x] + ssum[t] - s;
    if (n0 + 0 < N_NODES) { g_off[n0 + 0] = prefix; prefix += v0; }
    if (n0 + 1 < N_NODES) { g_off[n0 + 1] = prefix; prefix += v1; }
    if (n0 + 2 < N_NODES) { g_off[n0 + 2] = prefix; prefix += v2; }
    if (n0 + 3 < N_NODES) { g_off[n0 + 3] = prefix; }
}

// ---------------------------------------------------------------------------
// Scatter edges into CSR (no atomics), 4 edges/thread.
// ---------------------------------------------------------------------------
__global__ void scatter_kernel(const int* __restrict__ ei) {
    int t = blockIdx.x * blockDim.x + threadIdx.x;
    if (t >= N_EDGES / 4) return;
    int4 s4 = ((const int4*)ei)[t];
    int4 d4 = ((const int4*)(ei + N_EDGES))[t];
    int4 r4 = ((const int4*)g_rank)[t];
    int o0 = __ldg(&g_off[d4.x]);
    int o1 = __ldg(&g_off[d4.y]);
    int o2 = __ldg(&g_off[d4.z]);
    int o3 = __ldg(&g_off[d4.w]);
    g_srcs[o0 + r4.x] = s4.x;
    g_srcs[o1 + r4.y] = s4.y;
    g_srcs[o2 + r4.z] = s4.z;
    g_srcs[o3 + r4.w] = s4.w;
}

// ---------------------------------------------------------------------------
// Graph sizes via binary search (batch sorted)
// ---------------------------------------------------------------------------
__device__ __forceinline__ int lower_bound_batch(const int* b, int key) {
    int lo = 0, hi = N_NODES;
    while (lo < hi) {
        int mid = (lo + hi) >> 1;
        if (b[mid] < key) lo = mid + 1; else hi = mid;
    }
    return lo;
}
__global__ void count_kernel(const int* __restrict__ batch) {
    int g = blockIdx.x * blockDim.x + threadIdx.x;
    if (g >= N_GRAPHS) return;
    int a = lower_bound_batch(batch, g);
    int b = lower_bound_batch(batch, g + 1);
    g_gcnt[g] = (float)(b - a);
}

// ---------------------------------------------------------------------------
// Layer-1 gather-aggregate
// ---------------------------------------------------------------------------
__global__ void agg1_kernel(const float* __restrict__ x) {
    int gwarp = (blockIdx.x * blockDim.x + threadIdx.x) >> 5;
    int lane = threadIdx.x & 31;
    if (gwarp >= N_NODES) return;
    int start = g_off[gwarp], end = g_off[gwarp + 1];
    float a0 = 0, a1 = 0, a2 = 0, a3 = 0, a4 = 0;
    for (int e = start + lane; e < end; e += 32) {
        int s = g_srcs[e];
        uint4 v = g_xh[s];
        float2 p0 = __half22float2(*(__half2*)&v.x);
        float2 p1 = __half22float2(*(__half2*)&v.y);
        float2 p2 = __half22float2(*(__half2*)&v.z);
        a0 += p0.x; a1 += p0.y; a2 += p1.x; a3 += p1.y; a4 += p2.x;
    }
#pragma unroll
    for (int off = 16; off; off >>= 1) {
        a0 += __shfl_xor_sync(0xffffffffu, a0, off);
        a1 += __shfl_xor_sync(0xffffffffu, a1, off);
        a2 += __shfl_xor_sync(0xffffffffu, a2, off);
        a3 += __shfl_xor_sync(0xffffffffu, a3, off);
        a4 += __shfl_xor_sync(0xffffffffu, a4, off);
    }
    if (lane == 0) {
        const float* xn = x + gwarp * 5;
        float* z = g_z1 + gwarp * 5;
        z[0] = xn[0] + a0; z[1] = xn[1] + a1; z[2] = xn[2] + a2;
        z[3] = xn[3] + a3; z[4] = xn[4] + a4;
    }
}

// ---------------------------------------------------------------------------
// MLP1 (scalar, unchanged): h1 = relu(relu(z1@W1a+b1a)@W1b+b1b), fp16 out.
// ---------------------------------------------------------------------------
#define NPB 128
__global__ __launch_bounds__(256) void mlp1_kernel(
    const float* __restrict__ W1a, const float* __restrict__ b1a,
    const float* __restrict__ W1b, const float* __restrict__ b1b) {
    __shared__ float sWa[5 * HID];
    __shared__ float sWb[HID * HID];
    __shared__ float sba[HID];
    __shared__ float sbb[HID];
    __shared__ float sz[4][5][8];
    __shared__ float st[4][HID][8];

    int j = threadIdx.x;
    int r = threadIdx.y;
    int tid = r * 64 + j;

    for (int i = tid; i < 5 * HID; i += 256) sWa[i] = W1a[i];
    for (int i = tid; i < HID * HID; i += 256) sWb[i] = W1b[i];
    if (tid < HID) sba[tid] = b1a[tid];
    else if (tid < 2 * HID) sbb[tid - HID] = b1b[tid - HID];
    __syncthreads();

    int base = blockIdx.x * NPB;
    for (int it = 0; it < NPB / 32; ++it) {
        int n0 = base + it * 32 + r * 8;
        if (j < 40) {
            int i = j & 7, k = j >> 3;
            int n = n0 + i;
            sz[r][k][i] = (n < N_NODES) ? g_z1[n * 5 + k] : 0.0f;
        }
        __syncthreads();
        float bias = sba[j];
        float a0 = bias, a1 = bias, a2 = bias, a3 = bias;
        float a4 = bias, a5 = bias, a6 = bias, a7 = bias;
#pragma unroll
        for (int k = 0; k < 5; ++k) {
            float w = sWa[k * HID + j];
            float4 za = *(const float4*)&sz[r][k][0];
            float4 zb = *(const float4*)&sz[r][k][4];
            a0 += za.x * w; a1 += za.y * w; a2 += za.z * w; a3 += za.w * w;
            a4 += zb.x * w; a5 += zb.y * w; a6 += zb.z * w; a7 += zb.w * w;
        }
        float4 ta, tb;
        ta.x = fmaxf(a0, 0.0f); ta.y = fmaxf(a1, 0.0f);
        ta.z = fmaxf(a2, 0.0f); ta.w = fmaxf(a3, 0.0f);
        tb.x = fmaxf(a4, 0.0f); tb.y = fmaxf(a5, 0.0f);
        tb.z = fmaxf(a6, 0.0f); tb.w = fmaxf(a7, 0.0f);
        *(float4*)&st[r][j][0] = ta;
        *(float4*)&st[r][j][4] = tb;
        __syncthreads();
        float bias2 = sbb[j];
        float b0 = bias2, b1 = bias2, b2 = bias2, b3 = bias2;
        float b4 = bias2, b5 = bias2, b6 = bias2, b7 = bias2;
#pragma unroll
        for (int k = 0; k < HID; ++k) {
            float w = sWb[k * HID + j];
            float4 za = *(const float4*)&st[r][k][0];
            float4 zb = *(const float4*)&st[r][k][4];
            b0 += za.x * w; b1 += za.y * w; b2 += za.z * w; b3 += za.w * w;
            b4 += zb.x * w; b5 += zb.y * w; b6 += zb.z * w; b7 += zb.w * w;
        }
        __half* h1 = (__half*)g_h1h;
        if (n0 + 0 < N_NODES) h1[(n0 + 0) * HID + j] = __float2half(fmaxf(b0, 0.0f));
        if (n0 + 1 < N_NODES) h1[(n0 + 1) * HID + j] = __float2half(fmaxf(b1, 0.0f));
        if (n0 + 2 < N_NODES) h1[(n0 + 2) * HID + j] = __float2half(fmaxf(b2, 0.0f));
        if (n0 + 3 < N_NODES) h1[(n0 + 3) * HID + j] = __float2half(fmaxf(b3, 0.0f));
        if (n0 + 4 < N_NODES) h1[(n0 + 4) * HID + j] = __float2half(fmaxf(b4, 0.0f));
        if (n0 + 5 < N_NODES) h1[(n0 + 5) * HID + j] = __float2half(fmaxf(b5, 0.0f));
        if (n0 + 6 < N_NODES) h1[(n0 + 6) * HID + j] = __float2half(fmaxf(b6, 0.0f));
        if (n0 + 7 < N_NODES) h1[(n0 + 7) * HID + j] = __float2half(fmaxf(b7, 0.0f));
        __syncthreads();
    }
}

// ---------------------------------------------------------------------------
// Layer-2 gather-aggregate (fp16 gather, fp32 accumulate, fp16 z2 out), x4 ILP
// ---------------------------------------------------------------------------
__global__ void agg2_kernel() {
    int gwarp = (blockIdx.x * blockDim.x + threadIdx.x) >> 5;
    int lane = threadIdx.x & 31;
    if (gwarp >= N_NODES) return;
    int start = g_off[gwarp], end = g_off[gwarp + 1];
    float a0 = 0.0f, a1 = 0.0f;
    for (int b = start; b < end; b += 32) {
        int m = end - b; if (m > 32) m = 32;
        int myS = (b + lane < end) ? g_srcs[b + lane] : 0;
        int i = 0;
        for (; i + 3 < m; i += 4) {
            int s0 = __shfl_sync(0xffffffffu, myS, i);
            int s1 = __shfl_sync(0xffffffffu, myS, i + 1);
            int s2 = __shfl_sync(0xffffffffu, myS, i + 2);
            int s3 = __shfl_sync(0xffffffffu, myS, i + 3);
            float2 f0 = __half22float2(g_h1h[s0 * (HID/2) + lane]);
            float2 f1 = __half22float2(g_h1h[s1 * (HID/2) + lane]);
            float2 f2 = __half22float2(g_h1h[s2 * (HID/2) + lane]);
            float2 f3 = __half22float2(g_h1h[s3 * (HID/2) + lane]);
            a0 += f0.x + f1.x + f2.x + f3.x;
            a1 += f0.y + f1.y + f2.y + f3.y;
        }
        for (; i < m; ++i) {
            int s0 = __shfl_sync(0xffffffffu, myS, i);
            float2 f0 = __half22float2(g_h1h[s0 * (HID/2) + lane]);
            a0 += f0.x; a1 += f0.y;
        }
    }
    float2 hs = __half22float2(g_h1h[gwarp * (HID/2) + lane]);
    g_z2h[gwarp * (HID/2) + lane] = __floats2half2_rn(hs.x + a0, hs.y + a1);
}

// ---------------------------------------------------------------------------
// MLP2 via mma.sync (HMMA) + fused mean-pool scatter.
// Warp-tile = 16 nodes. 100000 = 16 * 6250 exactly.
// Weights staged in shared in fragment order (ushort4 per lane per tile).
// ---------------------------------------------------------------------------
__global__ __launch_bounds__(256) void mlp2_mma_kernel(
    const int* __restrict__ batch,
    const float* __restrict__ W2a, const float* __restrict__ b2a,
    const float* __restrict__ W2b, const float* __restrict__ b2b) {
    // frag-order weights: tile t = kt*8+nt; per lane 4 halfs {k0,k0+1,k0+8,k0+9} x col j
    __shared__ ushort4 sWa[32][32];
    __shared__ ushort4 sWb[32][32];
    __shared__ float sba[HID];
    __shared__ float sbb[HID];

    int tid = threadIdx.x;
    for (int idx = tid; idx < 1024; idx += 256) {
        int t = idx >> 5, ln = idx & 31;
        int kt = t >> 3, nt = t & 7;
        int j = nt * 8 + (ln >> 2);
        int k0 = kt * 16 + (ln & 3) * 2;
        ushort4 wa, wb;
        wa.x = __half_as_ushort(__float2half(W2a[(k0 + 0) * HID + j]));
        wa.y = __half_as_ushort(__float2half(W2a[(k0 + 1) * HID + j]));
        wa.z = __half_as_ushort(__float2half(W2a[(k0 + 8) * HID + j]));
        wa.w = __half_as_ushort(__float2half(W2a[(k0 + 9) * HID + j]));
        wb.x = __half_as_ushort(__float2half(W2b[(k0 + 0) * HID + j]));
        wb.y = __half_as_ushort(__float2half(W2b[(k0 + 1) * HID + j]));
        wb.z = __half_as_ushort(__float2half(W2b[(k0 + 8) * HID + j]));
        wb.w = __half_as_ushort(__float2half(W2b[(k0 + 9) * HID + j]));
        sWa[t][ln] = wa;
        sWb[t][ln] = wb;
    }
    if (tid < HID) sba[tid] = b2a[tid];
    else if (tid < 2 * HID) sbb[tid - HID] = b2b[tid - HID];
    __syncthreads();

    int warp = tid >> 5, lane = tid & 31;
    int wt = blockIdx.x * 8 + warp;
    if (wt >= WARP_TILES) return;
    int n0 = wt * 16;
    int r = lane >> 2;             // row in tile (0..7); rows r and r+8
    int cc = (lane & 3) * 2;       // col pair base

    // A fragments for layer a, from fp16 z2 (4 ktiles x 4 .b32)
    const __half* z2h = (const __half*)g_z2h;
    unsigned A[4][4];
#pragma unroll
    for (int kt = 0; kt < 4; ++kt) {
        int col = kt * 16 + cc;
        A[kt][0] = *(const unsigned*)&z2h[(n0 + r) * HID + col];
        A[kt][1] = *(const unsigned*)&z2h[(n0 + r + 8) * HID + col];
        A[kt][2] = *(const unsigned*)&z2h[(n0 + r) * HID + col + 8];
        A[kt][3] = *(const unsigned*)&z2h[(n0 + r + 8) * HID + col + 8];
    }

    // Layer a: T1 = relu(z2 @ W2a + b2a), kept as fp16 fragments
    unsigned T1[8][2];
#pragma unroll
    for (int nt = 0; nt < 8; ++nt) {
        float bias0 = sba[nt * 8 + cc];
        float bias1 = sba[nt * 8 + cc + 1];
        float c0 = bias0, c1 = bias1, c2 = bias0, c3 = bias1;
#pragma unroll
        for (int kt = 0; kt < 4; ++kt) {
            ushort4 w = sWa[kt * 8 + nt][lane];
            unsigned bq0 = (unsigned)w.x | ((unsigned)w.y << 16);
            unsigned bq1 = (unsigned)w.z | ((unsigned)w.w << 16);
            asm volatile(
                "mma.sync.aligned.m16n8k16.row.col.f32.f16.f16.f32 "
                "{%0,%1,%2,%3}, {%4,%5,%6,%7}, {%8,%9}, {%0,%1,%2,%3};"
                : "+f"(c0), "+f"(c1), "+f"(c2), "+f"(c3)
                : "r"(A[kt][0]), "r"(A[kt][1]), "r"(A[kt][2]), "r"(A[kt][3]),
                  "r"(bq0), "r"(bq1));
        }
        __half2 p01 = __floats2half2_rn(fmaxf(c0, 0.0f), fmaxf(c1, 0.0f));
        __half2 p23 = __floats2half2_rn(fmaxf(c2, 0.0f), fmaxf(c3, 0.0f));
        T1[nt][0] = *(unsigned*)&p01;
        T1[nt][1] = *(unsigned*)&p23;
    }

    int gA = batch[n0 + r];
    int gB = batch[n0 + r + 8];

    // Layer b: h2 = relu(T1 @ W2b + b2b); pool-scatter.
    // A2 frag for ktile kt comes from T1 ntiles 2kt (cols 0..7) and 2kt+1 (cols 8..15).
#pragma unroll
    for (int nt = 0; nt < 8; ++nt) {
        float bias0 = sbb[nt * 8 + cc];
        float bias1 = sbb[nt * 8 + cc + 1];
        float c0 = bias0, c1 = bias1, c2 = bias0, c3 = bias1;
#pragma unroll
        for (int kt = 0; kt < 4; ++kt) {
            ushort4 w = sWb[kt * 8 + nt][lane];
            unsigned bq0 = (unsigned)w.x | ((unsigned)w.y << 16);
            unsigned bq1 = (unsigned)w.z | ((unsigned)w.w << 16);
            asm volatile(
                "mma.sync.aligned.m16n8k16.row.col.f32.f16.f16.f32 "
                "{%0,%1,%2,%3}, {%4,%5,%6,%7}, {%8,%9}, {%0,%1,%2,%3};"
                : "+f"(c0), "+f"(c1), "+f"(c2), "+f"(c3)
                : "r"(T1[2 * kt][0]), "r"(T1[2 * kt][1]),
                  "r"(T1[2 * kt + 1][0]), "r"(T1[2 * kt + 1][1]),
                  "r"(bq0), "r"(bq1));
        }
        int col = nt * 8 + cc;
        atomicAdd(&g_gsum[gA * HID + col],     fmaxf(c0, 0.0f));
        atomicAdd(&g_gsum[gA * HID + col + 1], fmaxf(c1, 0.0f));
        atomicAdd(&g_gsum[gB * HID + col],     fmaxf(c2, 0.0f));
        atomicAdd(&g_gsum[gB * HID + col + 1], fmaxf(c3, 0.0f));
    }
}

// ---------------------------------------------------------------------------
// Head: out[g] = (gsum[g] / max(cnt,1)) @ Wc + bc
// ---------------------------------------------------------------------------
__global__ void head_kernel(const float* __restrict__ Wc,
                            const float* __restrict__ bc,
                            float* __restrict__ out) {
    int g = blockIdx.x * blockDim.x + threadIdx.x;
    if (g >= N_GRAPHS) return;
    float inv = 1.0f / fmaxf(g_gcnt[g], 1.0f);
    float a0 = bc[0], a1 = bc[1];
#pragma unroll
    for (int jj = 0; jj < HID; ++jj) {
        float p = g_gsum[g * HID + jj] * inv;
        a0 += p * Wc[jj * 2 + 0];
        a1 += p * Wc[jj * 2 + 1];
    }
    out[g * 2 + 0] = a0;
    out[g * 2 + 1] = a1;
}

// ---------------------------------------------------------------------------
extern "C" void kernel_launch(void* const* d_in, const int* in_sizes, int n_in,
                              void* d_out, int out_size) {
    const float* x   = (const float*)d_in[0];
    const int*   ei  = (const int*)d_in[1];
    const int*   bat = (const int*)d_in[2];
    const float* W1a = (const float*)d_in[3];
    const float* b1a = (const float*)d_in[4];
    const float* W1b = (const float*)d_in[5];
    const float* b1b = (const float*)d_in[6];
    const float* W2a = (const float*)d_in[7];
    const float* b2a = (const float*)d_in[8];
    const float* W2b = (const float*)d_in[9];
    const float* b2b = (const float*)d_in[10];
    const float* Wc  = (const float*)d_in[11];
    const float* bc  = (const float*)d_in[12];
    float* out = (float*)d_out;

    prep_kernel<<<(N_NODES + 4 + 255) / 256, 256>>>(x);
    hist_kernel<<<(N_EDGES / 4 + 255) / 256, 256>>>(ei);
    scanA_kernel<<<SCAN_BLOCKS, 256>>>();
    scanB_kernel<<<1, 128>>>();
    scanC_kernel<<<SCAN_BLOCKS, 256>>>();
    scatter_kernel<<<(N_EDGES / 4 + 255) / 256, 256>>>(ei);
    count_kernel<<<(N_GRAPHS + 255) / 256, 256>>>(bat);

    // layer 1
    agg1_kernel<<<(N_NODES * 32 + 255) / 256, 256>>>(x);
    mlp1_kernel<<<(N_NODES + NPB - 1) / NPB, dim3(64, 4)>>>(W1a, b1a, W1b, b1b);

    // layer 2
    agg2_kernel<<<(N_NODES * 32 + 255) / 256, 256>>>();
    mlp2_mma_kernel<<<(WARP_TILES + 7) / 8, 256>>>(bat, W2a, b2a, W2b, b2b);

    head_kernel<<<(N_GRAPHS + 255) / 256, 256>>>(Wc, bc, out);
}

// round 9
// speedup vs baseline: 1.8486x; 1.0965x over previous
#include <cuda_runtime.h>
#include <cuda_fp16.h>
#include <cstdint>

#define N_NODES 100000
#define N_EDGES 3200000
#define N_GRAPHS 1024
#define HID 64

#define SCAN_BLOCKS 98   // ceil(100000 / 1024)
#define WARP_TILES 6250  // 100000 / 16 (exact)

// ---------------------------------------------------------------------------
// Scratch (device globals; no allocations allowed)
// ---------------------------------------------------------------------------
__device__ int     g_deg[N_NODES + 4];
__device__ int     g_off[N_NODES + 1];
__device__ int     g_rank[N_EDGES];
__device__ int     g_srcs[N_EDGES];
__device__ int     g_bsum[SCAN_BLOCKS];
__device__ uint4   g_xh[N_NODES];            // x padded to 8 halfs
__device__ float   g_z1[N_NODES * 5 + 12];   // pad for staging overread
__device__ __half2 g_h1h[N_NODES * (HID/2)]; // layer-1 output (fp16)
__device__ __half2 g_z2h[N_NODES * (HID/2)]; // h1 + agg2 (fp16)
__device__ float   g_gsum[N_GRAPHS * HID];
__device__ float   g_gcnt[N_GRAPHS];

// ---------------------------------------------------------------------------
// Pack x into fp16 rows + zero deg/gsum. Grid covers N_NODES+4 threads.
// ---------------------------------------------------------------------------
__global__ void prep_kernel(const float* __restrict__ x) {
    int n = blockIdx.x * blockDim.x + threadIdx.x;
    if (n < N_NODES) {
        const float* xs = x + n * 5;
        __half2 h0 = __floats2half2_rn(xs[0], xs[1]);
        __half2 h1 = __floats2half2_rn(xs[2], xs[3]);
        __half2 h2 = __floats2half2_rn(xs[4], 0.0f);
        __half2 h3 = __floats2half2_rn(0.0f, 0.0f);
        uint4 v;
        v.x = *(unsigned*)&h0; v.y = *(unsigned*)&h1;
        v.z = *(unsigned*)&h2; v.w = *(unsigned*)&h3;
        g_xh[n] = v;
    }
    if (n < N_NODES + 4) g_deg[n] = 0;
    if (n < N_GRAPHS * HID) g_gsum[n] = 0.0f;
}

// ---------------------------------------------------------------------------
// Degree histogram (rank capture), 8 edges/thread.
// ---------------------------------------------------------------------------
__global__ void hist_kernel(const int* __restrict__ ei) {
    int t = blockIdx.x * blockDim.x + threadIdx.x;
    if (t >= N_EDGES / 8) return;
    const int4* dp = (const int4*)(ei + N_EDGES);
    int4 a = dp[2 * t], b = dp[2 * t + 1];
    int4 ra, rb;
    ra.x = atomicAdd(&g_deg[a.x], 1);
    ra.y = atomicAdd(&g_deg[a.y], 1);
    ra.z = atomicAdd(&g_deg[a.z], 1);
    ra.w = atomicAdd(&g_deg[a.w], 1);
    rb.x = atomicAdd(&g_deg[b.x], 1);
    rb.y = atomicAdd(&g_deg[b.y], 1);
    rb.z = atomicAdd(&g_deg[b.z], 1);
    rb.w = atomicAdd(&g_deg[b.w], 1);
    ((int4*)g_rank)[2 * t] = ra;
    ((int4*)g_rank)[2 * t + 1] = rb;
}

// ---------------------------------------------------------------------------
// Scan phase A: per-block sums (1024 nodes/block).
// ---------------------------------------------------------------------------
__global__ void scanA_kernel() {
    __shared__ int wsum[8];
    int t = threadIdx.x;
    int n0 = blockIdx.x * 1024 + t * 4;
    int s = 0;
    if (n0 + 3 < N_NODES) {
        int4 v = *(const int4*)&g_deg[n0];
        s = v.x + v.y + v.z + v.w;
    } else {
#pragma unroll
        for (int i = 0; i < 4; ++i)
            if (n0 + i < N_NODES) s += g_deg[n0 + i];
    }
    int lane = t & 31;
#pragma unroll
    for (int off = 16; off; off >>= 1) s += __shfl_xor_sync(0xffffffffu, s, off);
    if (lane == 0) wsum[t >> 5] = s;
    __syncthreads();
    if (t < 8) {
        int v = wsum[t];
#pragma unroll
        for (int off = 4; off; off >>= 1) v += __shfl_xor_sync(0xffu, v, off);
        if (t == 0) g_bsum[blockIdx.x] = v;
    }
}

// ---------------------------------------------------------------------------
// Scan phase C (with inlined phase B): every block re-scans the 98 partials.
// ---------------------------------------------------------------------------
__global__ void scanC_kernel() {
    __shared__ int sbs[128];
    __shared__ int ssum[256];
    int t = threadIdx.x;
    // inline scan of block sums (inclusive), done redundantly per block
    if (t < 128) sbs[t] = (t < SCAN_BLOCKS) ? g_bsum[t] : 0;
    __syncthreads();
    for (int d = 1; d < 128; d <<= 1) {
        int u = (t >= d && t < 128) ? sbs[t - d] : 0;
        __syncthreads();
        if (t < 128) sbs[t] += u;
        __syncthreads();
    }
    int boff = (blockIdx.x == 0) ? 0 : sbs[blockIdx.x - 1];
    if (blockIdx.x == 0 && t == 0) g_off[N_NODES] = sbs[SCAN_BLOCKS - 1];

    int n0 = blockIdx.x * 1024 + t * 4;
    int v0 = 0, v1 = 0, v2 = 0, v3 = 0;
    if (n0 + 3 < N_NODES) {
        int4 v = *(const int4*)&g_deg[n0];
        v0 = v.x; v1 = v.y; v2 = v.z; v3 = v.w;
    } else {
        if (n0 + 0 < N_NODES) v0 = g_deg[n0 + 0];
        if (n0 + 1 < N_NODES) v1 = g_deg[n0 + 1];
        if (n0 + 2 < N_NODES) v2 = g_deg[n0 + 2];
        if (n0 + 3 < N_NODES) v3 = g_deg[n0 + 3];
    }
    int s = v0 + v1 + v2 + v3;
    ssum[t] = s;
    __syncthreads();
    for (int d = 1; d < 256; d <<= 1) {
        int u = (t >= d) ? ssum[t - d] : 0;
        __syncthreads();
        ssum[t] += u;
        __syncthreads();
    }
    int prefix = boff + ssum[t] - s;
    if (n0 + 0 < N_NODES) { g_off[n0 + 0] = prefix; prefix += v0; }
    if (n0 + 1 < N_NODES) { g_off[n0 + 1] = prefix; prefix += v1; }
    if (n0 + 2 < N_NODES) { g_off[n0 + 2] = prefix; prefix += v2; }
    if (n0 + 3 < N_NODES) { g_off[n0 + 3] = prefix; }
}

// ---------------------------------------------------------------------------
// Scatter edges into CSR (no atomics), 8 edges/thread.
// ---------------------------------------------------------------------------
__global__ void scatter_kernel(const int* __restrict__ ei) {
    int t = blockIdx.x * blockDim.x + threadIdx.x;
    if (t >= N_EDGES / 8) return;
    const int4* sp = (const int4*)ei;
    const int4* dp = (const int4*)(ei + N_EDGES);
    const int4* rp = (const int4*)g_rank;
    int4 sa = sp[2 * t], sb = sp[2 * t + 1];
    int4 da = dp[2 * t], db = dp[2 * t + 1];
    int4 ra = rp[2 * t], rb = rp[2 * t + 1];
    g_srcs[__ldg(&g_off[da.x]) + ra.x] = sa.x;
    g_srcs[__ldg(&g_off[da.y]) + ra.y] = sa.y;
    g_srcs[__ldg(&g_off[da.z]) + ra.z] = sa.z;
    g_srcs[__ldg(&g_off[da.w]) + ra.w] = sa.w;
    g_srcs[__ldg(&g_off[db.x]) + rb.x] = sb.x;
    g_srcs[__ldg(&g_off[db.y]) + rb.y] = sb.y;
    g_srcs[__ldg(&g_off[db.z]) + rb.z] = sb.z;
    g_srcs[__ldg(&g_off[db.w]) + rb.w] = sb.w;
}

// ---------------------------------------------------------------------------
// Graph sizes via binary search (batch sorted)
// ---------------------------------------------------------------------------
__device__ __forceinline__ int lower_bound_batch(const int* b, int key) {
    int lo = 0, hi = N_NODES;
    while (lo < hi) {
        int mid = (lo + hi) >> 1;
        if (b[mid] < key) lo = mid + 1; else hi = mid;
    }
    return lo;
}
__global__ void count_kernel(const int* __restrict__ batch) {
    int g = blockIdx.x * blockDim.x + threadIdx.x;
    if (g >= N_GRAPHS) return;
    int a = lower_bound_batch(batch, g);
    int b = lower_bound_batch(batch, g + 1);
    g_gcnt[g] = (float)(b - a);
}

// ---------------------------------------------------------------------------
// Layer-1 gather-aggregate: z1[n] = x[n] + sum x[s] (fp32 out)
// ---------------------------------------------------------------------------
__global__ void agg1_kernel(const float* __restrict__ x) {
    int gwarp = (blockIdx.x * blockDim.x + threadIdx.x) >> 5;
    int lane = threadIdx.x & 31;
    if (gwarp >= N_NODES) return;
    int start = g_off[gwarp], end = g_off[gwarp + 1];
    float a0 = 0, a1 = 0, a2 = 0, a3 = 0, a4 = 0;
    for (int e = start + lane; e < end; e += 32) {
        int s = g_srcs[e];
        uint4 v = g_xh[s];
        float2 p0 = __half22float2(*(__half2*)&v.x);
        float2 p1 = __half22float2(*(__half2*)&v.y);
        float2 p2 = __half22float2(*(__half2*)&v.z);
        a0 += p0.x; a1 += p0.y; a2 += p1.x; a3 += p1.y; a4 += p2.x;
    }
#pragma unroll
    for (int off = 16; off; off >>= 1) {
        a0 += __shfl_xor_sync(0xffffffffu, a0, off);
        a1 += __shfl_xor_sync(0xffffffffu, a1, off);
        a2 += __shfl_xor_sync(0xffffffffu, a2, off);
        a3 += __shfl_xor_sync(0xffffffffu, a3, off);
        a4 += __shfl_xor_sync(0xffffffffu, a4, off);
    }
    if (lane == 0) {
        const float* xn = x + gwarp * 5;
        float* z = g_z1 + gwarp * 5;
        z[0] = xn[0] + a0; z[1] = xn[1] + a1; z[2] = xn[2] + a2;
        z[3] = xn[3] + a3; z[4] = xn[4] + a4;
    }
}

// ---------------------------------------------------------------------------
// MLP1 hybrid: layer-a scalar fp32 -> T1 fragments; layer-b via HMMA.
// Block = 256 threads = 8 warps x 16 nodes = 128 nodes.
// ---------------------------------------------------------------------------
__global__ __launch_bounds__(256) void mlp1_mma_kernel(
    const float* __restrict__ W1a, const float* __restrict__ b1a,
    const float* __restrict__ W1b, const float* __restrict__ b1b) {
    __shared__ float sWa[5][HID];
    __shared__ ushort4 sWb[32][32];   // frag-order fp16 W1b
    __shared__ float sba[HID];
    __shared__ float sbb[HID];
    __shared__ float sz[5][128];      // z1 staged [k][node-in-block]

    int tid = threadIdx.x;
    for (int i = tid; i < 5 * HID; i += 256) sWa[i / HID][i % HID] = W1a[i];
    for (int idx = tid; idx < 1024; idx += 256) {
        int t = idx >> 5, ln = idx & 31;
        int kt = t >> 3, nt = t & 7;
        int j = nt * 8 + (ln >> 2);
        int k0 = kt * 16 + (ln & 3) * 2;
        ushort4 wb;
        wb.x = __half_as_ushort(__float2half(W1b[(k0 + 0) * HID + j]));
        wb.y = __half_as_ushort(__float2half(W1b[(k0 + 1) * HID + j]));
        wb.z = __half_as_ushort(__float2half(W1b[(k0 + 8) * HID + j]));
        wb.w = __half_as_ushort(__float2half(W1b[(k0 + 9) * HID + j]));
        sWb[t][ln] = wb;
    }
    if (tid < HID) sba[tid] = b1a[tid];
    else if (tid < 2 * HID) sbb[tid - HID] = b1b[tid - HID];

    int base = blockIdx.x * 128;
    // stage z1: coalesced read of 640 floats, write [k][n]
    for (int i = tid; i < 640; i += 256) {
        int n = i / 5, k = i % 5;
        long long gi = (long long)base * 5 + i;
        sz[k][n] = (gi < (long long)N_NODES * 5) ? g_z1[gi] : 0.0f;
    }
    __syncthreads();

    int warp = tid >> 5, lane = tid & 31;
    int n0 = base + warp * 16;
    if (n0 >= N_NODES) return;   // 100000 % 16 == 0, so active tiles are full
    int r = lane >> 2;
    int cc = (lane & 3) * 2;
    int nb = warp * 16;

    float zr[5], zR[5];
#pragma unroll
    for (int k = 0; k < 5; ++k) {
        zr[k] = sz[k][nb + r];
        zR[k] = sz[k][nb + r + 8];
    }

    // layer a scalar -> T1 fp16 fragments
    unsigned T1[8][2];
#pragma unroll
    for (int nt = 0; nt < 8; ++nt) {
        int j0 = nt * 8 + cc;
        float c0 = sba[j0], c1 = sba[j0 + 1];
        float c2 = c0, c3 = c1;
#pragma unroll
        for (int k = 0; k < 5; ++k) {
            float w0 = sWa[k][j0], w1 = sWa[k][j0 + 1];
            c0 += zr[k] * w0; c1 += zr[k] * w1;
            c2 += zR[k] * w0; c3 += zR[k] * w1;
        }
        __half2 p01 = __floats2half2_rn(fmaxf(c0, 0.0f), fmaxf(c1, 0.0f));
        __half2 p23 = __floats2half2_rn(fmaxf(c2, 0.0f), fmaxf(c3, 0.0f));
        T1[nt][0] = *(unsigned*)&p01;
        T1[nt][1] = *(unsigned*)&p23;
    }

    // layer b via HMMA -> h1 fp16
#pragma unroll
    for (int nt = 0; nt < 8; ++nt) {
        float bias0 = sbb[nt * 8 + cc];
        float bias1 = sbb[nt * 8 + cc + 1];
        float c0 = bias0, c1 = bias1, c2 = bias0, c3 = bias1;
#pragma unroll
        for (int kt = 0; kt < 4; ++kt) {
            ushort4 w = sWb[kt * 8 + nt][lane];
            unsigned bq0 = (unsigned)w.x | ((unsigned)w.y << 16);
            unsigned bq1 = (unsigned)w.z | ((unsigned)w.w << 16);
            asm volatile(
                "mma.sync.aligned.m16n8k16.row.col.f32.f16.f16.f32 "
                "{%0,%1,%2,%3}, {%4,%5,%6,%7}, {%8,%9}, {%0,%1,%2,%3};"
                : "+f"(c0), "+f"(c1), "+f"(c2), "+f"(c3)
                : "r"(T1[2 * kt][0]), "r"(T1[2 * kt][1]),
                  "r"(T1[2 * kt + 1][0]), "r"(T1[2 * kt + 1][1]),
                  "r"(bq0), "r"(bq1));
        }
        __half2 p01 = __floats2half2_rn(fmaxf(c0, 0.0f), fmaxf(c1, 0.0f));
        __half2 p23 = __floats2half2_rn(fmaxf(c2, 0.0f), fmaxf(c3, 0.0f));
        int colh = (nt * 8 + cc) >> 1;   // half2 index
        g_h1h[(n0 + r) * (HID / 2) + colh] = p01;
        g_h1h[(n0 + r + 8) * (HID / 2) + colh] = p23;
    }
}

// ---------------------------------------------------------------------------
// Layer-2 gather-aggregate (fp16 gather, fp32 accumulate, fp16 out), ILP 8.
// ---------------------------------------------------------------------------
__global__ void agg2_kernel() {
    int gwarp = (blockIdx.x * blockDim.x + threadIdx.x) >> 5;
    int lane = threadIdx.x & 31;
    if (gwarp >= N_NODES) return;
    int start = g_off[gwarp], end = g_off[gwarp + 1];
    float a0 = 0.0f, a1 = 0.0f;
    for (int b = start; b < end; b += 32) {
        int m = end - b; if (m > 32) m = 32;
        int myS = (b + lane < end) ? g_srcs[b + lane] : 0;
        int i = 0;
        for (; i + 7 < m; i += 8) {
            float2 f0 = __half22float2(g_h1h[__shfl_sync(0xffffffffu, myS, i + 0) * (HID/2) + lane]);
            float2 f1 = __half22float2(g_h1h[__shfl_sync(0xffffffffu, myS, i + 1) * (HID/2) + lane]);
            float2 f2 = __half22float2(g_h1h[__shfl_sync(0xffffffffu, myS, i + 2) * (HID/2) + lane]);
            float2 f3 = __half22float2(g_h1h[__shfl_sync(0xffffffffu, myS, i + 3) * (HID/2) + lane]);
            float2 f4 = __half22float2(g_h1h[__shfl_sync(0xffffffffu, myS, i + 4) * (HID/2) + lane]);
            float2 f5 = __half22float2(g_h1h[__shfl_sync(0xffffffffu, myS, i + 5) * (HID/2) + lane]);
            float2 f6 = __half22float2(g_h1h[__shfl_sync(0xffffffffu, myS, i + 6) * (HID/2) + lane]);
            float2 f7 = __half22float2(g_h1h[__shfl_sync(0xffffffffu, myS, i + 7) * (HID/2) + lane]);
            a0 += ((f0.x + f1.x) + (f2.x + f3.x)) + ((f4.x + f5.x) + (f6.x + f7.x));
            a1 += ((f0.y + f1.y) + (f2.y + f3.y)) + ((f4.y + f5.y) + (f6.y + f7.y));
        }
        for (; i < m; ++i) {
            float2 f0 = __half22float2(g_h1h[__shfl_sync(0xffffffffu, myS, i) * (HID/2) + lane]);
            a0 += f0.x; a1 += f0.y;
        }
    }
    float2 hs = __half22float2(g_h1h[gwarp * (HID/2) + lane]);
    g_z2h[gwarp * (HID/2) + lane] = __floats2half2_rn(hs.x + a0, hs.y + a1);
}

// ---------------------------------------------------------------------------
// MLP2 via HMMA + fused mean-pool scatter (unchanged from R8).
// ---------------------------------------------------------------------------
__global__ __launch_bounds__(256) void mlp2_mma_kernel(
    const int* __restrict__ batch,
    const float* __restrict__ W2a, const float* __restrict__ b2a,
    const float* __restrict__ W2b, const float* __restrict__ b2b) {
    __shared__ ushort4 sWa[32][32];
    __shared__ ushort4 sWb[32][32];
    __shared__ float sba[HID];
    __shared__ float sbb[HID];

    int tid = threadIdx.x;
    for (int idx = tid; idx < 1024; idx += 256) {
        int t = idx >> 5, ln = idx & 31;
        int kt = t >> 3, nt = t & 7;
        int j = nt * 8 + (ln >> 2);
        int k0 = kt * 16 + (ln & 3) * 2;
        ushort4 wa, wb;
        wa.x = __half_as_ushort(__float2half(W2a[(k0 + 0) * HID + j]));
        wa.y = __half_as_ushort(__float2half(W2a[(k0 + 1) * HID + j]));
        wa.z = __half_as_ushort(__float2half(W2a[(k0 + 8) * HID + j]));
        wa.w = __half_as_ushort(__float2half(W2a[(k0 + 9) * HID + j]));
        wb.x = __half_as_ushort(__float2half(W2b[(k0 + 0) * HID + j]));
        wb.y = __half_as_ushort(__float2half(W2b[(k0 + 1) * HID + j]));
        wb.z = __half_as_ushort(__float2half(W2b[(k0 + 8) * HID + j]));
        wb.w = __half_as_ushort(__float2half(W2b[(k0 + 9) * HID + j]));
        sWa[t][ln] = wa;
        sWb[t][ln] = wb;
    }
    if (tid < HID) sba[tid] = b2a[tid];
    else if (tid < 2 * HID) sbb[tid - HID] = b2b[tid - HID];
    __syncthreads();

    int warp = tid >> 5, lane = tid & 31;
    int wt = blockIdx.x * 8 + warp;
    if (wt >= WARP_TILES) return;
    int n0 = wt * 16;
    int r = lane >> 2;
    int cc = (lane & 3) * 2;

    const __half* z2h = (const __half*)g_z2h;
    unsigned A[4][4];
#pragma unroll
    for (int kt = 0; kt < 4; ++kt) {
        int col = kt * 16 + cc;
        A[kt][0] = *(const unsigned*)&z2h[(n0 + r) * HID + col];
        A[kt][1] = *(const unsigned*)&z2h[(n0 + r + 8) * HID + col];
        A[kt][2] = *(const unsigned*)&z2h[(n0 + r) * HID + col + 8];
        A[kt][3] = *(const unsigned*)&z2h[(n0 + r + 8) * HID + col + 8];
    }

    unsigned T1[8][2];
#pragma unroll
    for (int nt = 0; nt < 8; ++nt) {
        float bias0 = sba[nt * 8 + cc];
        float bias1 = sba[nt * 8 + cc + 1];
        float c0 = bias0, c1 = bias1, c2 = bias0, c3 = bias1;
#pragma unroll
        for (int kt = 0; kt < 4; ++kt) {
            ushort4 w = sWa[kt * 8 + nt][lane];
            unsigned bq0 = (unsigned)w.x | ((unsigned)w.y << 16);
            unsigned bq1 = (unsigned)w.z | ((unsigned)w.w << 16);
            asm volatile(
                "mma.sync.aligned.m16n8k16.row.col.f32.f16.f16.f32 "
                "{%0,%1,%2,%3}, {%4,%5,%6,%7}, {%8,%9}, {%0,%1,%2,%3};"
                : "+f"(c0), "+f"(c1), "+f"(c2), "+f"(c3)
                : "r"(A[kt][0]), "r"(A[kt][1]), "r"(A[kt][2]), "r"(A[kt][3]),
                  "r"(bq0), "r"(bq1));
        }
        __half2 p01 = __floats2half2_rn(fmaxf(c0, 0.0f), fmaxf(c1, 0.0f));
        __half2 p23 = __floats2half2_rn(fmaxf(c2, 0.0f), fmaxf(c3, 0.0f));
        T1[nt][0] = *(unsigned*)&p01;
        T1[nt][1] = *(unsigned*)&p23;
    }

    int gA = batch[n0 + r];
    int gB = batch[n0 + r + 8];

#pragma unroll
    for (int nt = 0; nt < 8; ++nt) {
        float bias0 = sbb[nt * 8 + cc];
        float bias1 = sbb[nt * 8 + cc + 1];
        float c0 = bias0, c1 = bias1, c2 = bias0, c3 = bias1;
#pragma unroll
        for (int kt = 0; kt < 4; ++kt) {
            ushort4 w = sWb[kt * 8 + nt][lane];
            unsigned bq0 = (unsigned)w.x | ((unsigned)w.y << 16);
            unsigned bq1 = (unsigned)w.z | ((unsigned)w.w << 16);
            asm volatile(
                "mma.sync.aligned.m16n8k16.row.col.f32.f16.f16.f32 "
                "{%0,%1,%2,%3}, {%4,%5,%6,%7}, {%8,%9}, {%0,%1,%2,%3};"
                : "+f"(c0), "+f"(c1), "+f"(c2), "+f"(c3)
                : "r"(T1[2 * kt][0]), "r"(T1[2 * kt][1]),
                  "r"(T1[2 * kt + 1][0]), "r"(T1[2 * kt + 1][1]),
                  "r"(bq0), "r"(bq1));
        }
        int col = nt * 8 + cc;
        atomicAdd(&g_gsum[gA * HID + col],     fmaxf(c0, 0.0f));
        atomicAdd(&g_gsum[gA * HID + col + 1], fmaxf(c1, 0.0f));
        atomicAdd(&g_gsum[gB * HID + col],     fmaxf(c2, 0.0f));
        atomicAdd(&g_gsum[gB * HID + col + 1], fmaxf(c3, 0.0f));
    }
}

// ---------------------------------------------------------------------------
// Head: out[g] = (gsum[g] / max(cnt,1)) @ Wc + bc
// ---------------------------------------------------------------------------
__global__ void head_kernel(const float* __restrict__ Wc,
                            const float* __restrict__ bc,
                            float* __restrict__ out) {
    int g = blockIdx.x * blockDim.x + threadIdx.x;
    if (g >= N_GRAPHS) return;
    float inv = 1.0f / fmaxf(g_gcnt[g], 1.0f);
    float a0 = bc[0], a1 = bc[1];
#pragma unroll
    for (int jj = 0; jj < HID; ++jj) {
        float p = g_gsum[g * HID + jj] * inv;
        a0 += p * Wc[jj * 2 + 0];
        a1 += p * Wc[jj * 2 + 1];
    }
    out[g * 2 + 0] = a0;
    out[g * 2 + 1] = a1;
}

// ---------------------------------------------------------------------------
extern "C" void kernel_launch(void* const* d_in, const int* in_sizes, int n_in,
                              void* d_out, int out_size) {
    const float* x   = (const float*)d_in[0];
    const int*   ei  = (const int*)d_in[1];
    const int*   bat = (const int*)d_in[2];
    const float* W1a = (const float*)d_in[3];
    const float* b1a = (const float*)d_in[4];
    const float* W1b = (const float*)d_in[5];
    const float* b1b = (const float*)d_in[6];
    const float* W2a = (const float*)d_in[7];
    const float* b2a = (const float*)d_in[8];
    const float* W2b = (const float*)d_in[9];
    const float* b2b = (const float*)d_in[10];
    const float* Wc  = (const float*)d_in[11];
    const float* bc  = (const float*)d_in[12];
    float* out = (float*)d_out;

    prep_kernel<<<(N_NODES + 4 + 255) / 256, 256>>>(x);
    hist_kernel<<<(N_EDGES / 8 + 255) / 256, 256>>>(ei);
    scanA_kernel<<<SCAN_BLOCKS, 256>>>();
    scanC_kernel<<<SCAN_BLOCKS, 256>>>();
    scatter_kernel<<<(N_EDGES / 8 + 255) / 256, 256>>>(ei);
    count_kernel<<<(N_GRAPHS + 255) / 256, 256>>>(bat);

    // layer 1
    agg1_kernel<<<(N_NODES * 32 + 255) / 256, 256>>>(x);
    mlp1_mma_kernel<<<(N_NODES + 127) / 128, 256>>>(W1a, b1a, W1b, b1b);

    // layer 2
    agg2_kernel<<<(N_NODES * 32 + 255) / 256, 256>>>();
    mlp2_mma_kernel<<<(WARP_TILES + 7) / 8, 256>>>(bat, W2a, b2a, W2b, b2b);

    head_kernel<<<(N_GRAPHS + 255) / 256, 256>>>(Wc, bc, out);
}